// round 10
// baseline (speedup 1.0000x reference)
#include <cuda_runtime.h>
#include <cstdint>

// Problem constants
#define SS        196              // S*S = 14*14
#define DCH       30               // 5*B + C
#define NBATCH    4096
#define IMG_FLOATS (DCH * SS)      // 5880 floats per image per tensor
#define IMG_BYTES  (IMG_FLOATS * 4) // 23520 bytes (multiple of 16)
#define STAGE_BYTES (2 * IMG_BYTES) // pred + tgt per stage = 47040
#define BLOCK     256
#define GRIDP     304              // 152 SMs * 2 blocks, persistent
#define LAMBDA_COORD 5.0f
#define LAMBDA_NOOBJ 0.5f

__device__ float        g_accum  = 0.0f;
__device__ unsigned int g_ticket = 0;

__device__ __forceinline__ uint32_t smem_u32(const void* p) {
    uint32_t a;
    asm("{ .reg .u64 t; cvta.to.shared.u64 t, %1; cvt.u32.u64 %0, t; }"
        : "=r"(a) : "l"(p));
    return a;
}

__device__ __forceinline__ void mbar_init(uint32_t mbar, uint32_t count) {
    asm volatile("mbarrier.init.shared.b64 [%0], %1;" :: "r"(mbar), "r"(count) : "memory");
}
__device__ __forceinline__ void mbar_expect_tx(uint32_t mbar, uint32_t bytes) {
    asm volatile("mbarrier.arrive.expect_tx.shared.b64 _, [%0], %1;"
                 :: "r"(mbar), "r"(bytes) : "memory");
}
__device__ __forceinline__ void bulk_g2s(uint32_t dst_smem, const void* src, uint32_t bytes,
                                         uint32_t mbar) {
    asm volatile(
        "cp.async.bulk.shared::cluster.global.mbarrier::complete_tx::bytes "
        "[%0], [%1], %2, [%3];"
        :: "r"(dst_smem), "l"(src), "r"(bytes), "r"(mbar) : "memory");
}
__device__ __forceinline__ void mbar_wait(uint32_t mbar, uint32_t parity) {
    uint32_t done;
    asm volatile(
        "{\n\t"
        ".reg .pred p;\n\t"
        "mbarrier.try_wait.parity.acquire.cta.shared::cta.b64 p, [%1], %2;\n\t"
        "selp.b32 %0, 1, 0, p;\n\t"
        "}"
        : "=r"(done) : "r"(mbar), "r"(parity) : "memory");
    if (!done) {
        asm volatile(
            "{\n\t"
            ".reg .pred P1;\n\t"
            "WL_%=:\n\t"
            "mbarrier.try_wait.parity.acquire.cta.shared::cta.b64 P1, [%0], %1, 0x989680;\n\t"
            "@P1 bra.uni WD_%=;\n\t"
            "bra.uni WL_%=;\n\t"
            "WD_%=:\n\t"
            "}"
            :: "r"(mbar), "r"(parity) : "memory");
    }
}

__global__ void __launch_bounds__(BLOCK, 2) yolo_tma_kernel(
    const float* __restrict__ pred,
    const float* __restrict__ tgt,
    float* __restrict__ out)
{
    extern __shared__ float sm[];            // 2 stages x (pred image + tgt image)
    __shared__ unsigned long long mbar_store[2];

    const int tid = threadIdx.x;
    const int b   = blockIdx.x;
    const uint32_t smb = smem_u32(sm);
    const uint32_t mb0 = smem_u32(&mbar_store[0]);
    const uint32_t mb1 = smem_u32(&mbar_store[1]);

    // image range for this block: blocks 0..143 get 14 images, rest get 13
    const int start = b * 13 + min(b, 144);
    const int cnt   = 13 + (b < 144 ? 1 : 0);

    if (tid == 0) {
        mbar_init(mb0, 1);
        mbar_init(mb1, 1);
    }
    __syncthreads();

    // prologue: issue stage 0 (image `start`)
    if (tid == 0) {
        mbar_expect_tx(mb0, STAGE_BYTES);
        bulk_g2s(smb,                 pred + (size_t)start * IMG_FLOATS, IMG_BYTES, mb0);
        bulk_g2s(smb + IMG_BYTES,     tgt  + (size_t)start * IMG_FLOATS, IMG_BYTES, mb0);
    }

    const float invS = 1.0f / 14.0f;
    float acc = 0.0f;

    for (int it = 0; it < cnt; ++it) {
        const int s = it & 1;
        const uint32_t mbs = s ? mb1 : mb0;

        // issue next stage before waiting on this one (overlap)
        if (tid == 0 && (it + 1) < cnt) {
            const int s1 = s ^ 1;
            const uint32_t mbn = s1 ? mb1 : mb0;
            const uint32_t d = smb + (uint32_t)s1 * STAGE_BYTES;
            const size_t   g = (size_t)(start + it + 1) * IMG_FLOATS;
            mbar_expect_tx(mbn, STAGE_BYTES);
            bulk_g2s(d,             pred + g, IMG_BYTES, mbn);
            bulk_g2s(d + IMG_BYTES, tgt  + g, IMG_BYTES, mbn);
        }

        // wait for this stage's data
        mbar_wait(mbs, (it >> 1) & 1);

        if (tid < SS) {
            const float* __restrict__ smP = sm + s * (2 * IMG_FLOATS);
            const float* __restrict__ smT = smP + IMG_FLOATS;

            float pp[10], tp[10];
#pragma unroll
            for (int d = 0; d < 10; ++d) {
                pp[d] = smP[d * SS + tid];
                tp[d] = smT[d * SS + tid];
            }

            const float tconf = tp[4];
            const float obj   = (tconf > 0.0f) ? 1.0f : 0.0f;
            const float noobj = (tconf == 0.0f) ? 1.0f : 0.0f;

            float cls = 0.0f;
#pragma unroll
            for (int d = 10; d < DCH; ++d) {
                float dv = smP[d * SS + tid] - smT[d * SS + tid];
                cls += dv * dv;
            }

            const float d0 = pp[4] - tp[4];
            const float d1 = pp[9] - tp[9];
            const float l_noobj = noobj * (d0 * d0 + d1 * d1);

            const float t_cx = tp[0] * invS, t_cy = tp[1] * invS;
            const float t_ltx = t_cx - 0.5f * tp[2];
            const float t_lty = t_cy - 0.5f * tp[3];
            const float t_rbx = t_cx + 0.5f * tp[2];
            const float t_rby = t_cy + 0.5f * tp[3];
            const float t_area = (t_rbx - t_ltx) * (t_rby - t_lty);

            float iou[2];
#pragma unroll
            for (int bb = 0; bb < 2; ++bb) {
                const float px = pp[5 * bb + 0], py = pp[5 * bb + 1];
                const float pw = pp[5 * bb + 2], ph = pp[5 * bb + 3];
                const float p_cx = px * invS, p_cy = py * invS;
                const float p_ltx = p_cx - 0.5f * pw;
                const float p_lty = p_cy - 0.5f * ph;
                const float p_rbx = p_cx + 0.5f * pw;
                const float p_rby = p_cy + 0.5f * ph;
                const float wx = fmaxf(fminf(t_rbx, p_rbx) - fmaxf(t_ltx, p_ltx), 0.0f);
                const float wy = fmaxf(fminf(t_rby, p_rby) - fmaxf(t_lty, p_lty), 0.0f);
                const float inter  = wx * wy;
                const float p_area = (p_rbx - p_ltx) * (p_rby - p_lty);
                float un = t_area + p_area - inter;
                if (un == 0.0f) un = 1.0f;
                iou[bb] = inter / un;
            }

            const int   r       = (iou[1] > iou[0]) ? 1 : 0;
            const float max_iou = fmaxf(iou[0], iou[1]);

            const float e0 = pp[5 * r + 0] - tp[5 * r + 0];
            const float e1 = pp[5 * r + 1] - tp[5 * r + 1];
            const float e2 = pp[5 * r + 2] - tp[5 * r + 2];
            const float e3 = pp[5 * r + 3] - tp[5 * r + 3];
            const float l_coord = e0 * e0 + e1 * e1 + e2 * e2 + e3 * e3;
            const float ec = pp[5 * r + 4] - max_iou;

            acc += obj * (LAMBDA_COORD * l_coord + ec * ec + cls)
                 + LAMBDA_NOOBJ * l_noobj;
        }

        // all reads of stage s done before it can be overwritten at iter it+2
        __syncthreads();
    }

    // ---- block reduction ----
    __shared__ float warp_sums[BLOCK / 32];
#pragma unroll
    for (int off = 16; off > 0; off >>= 1)
        acc += __shfl_xor_sync(0xFFFFFFFFu, acc, off);
    const int lane = tid & 31;
    const int wid  = tid >> 5;
    if (lane == 0) warp_sums[wid] = acc;
    __syncthreads();

    // ---- single-warp epilogue; no barrier after atomics ----
    if (wid == 0) {
        float v = (lane < BLOCK / 32) ? warp_sums[lane] : 0.0f;
#pragma unroll
        for (int off = 4; off > 0; off >>= 1)
            v += __shfl_xor_sync(0xFFFFFFFFu, v, off);
        if (lane == 0) {
            atomicAdd(&g_accum, v * (1.0f / (float)NBATCH));
            unsigned int tk;
            asm volatile("atom.acq_rel.gpu.global.add.u32 %0, [%1], %2;"
                         : "=r"(tk)
                         : "l"(&g_ticket), "r"(1u)
                         : "memory");
            if (tk == GRIDP - 1) {
                float tot;
                asm volatile("ld.acquire.gpu.global.f32 %0, [%1];"
                             : "=f"(tot)
                             : "l"(&g_accum)
                             : "memory");
                out[0] = tot;
                g_accum  = 0.0f;   // reset for next graph replay
                g_ticket = 0;
            }
        }
    }
}

extern "C" void kernel_launch(void* const* d_in, const int* in_sizes, int n_in,
                              void* d_out, int out_size)
{
    const float* pred = (const float*)d_in[0];
    const float* tgt  = (const float*)d_in[1];
    float* out = (float*)d_out;

    const int smem_dyn = 2 * STAGE_BYTES;  // 94080 bytes
    cudaFuncSetAttribute(yolo_tma_kernel,
                         cudaFuncAttributeMaxDynamicSharedMemorySize, smem_dyn);
    yolo_tma_kernel<<<GRIDP, BLOCK, smem_dyn>>>(pred, tgt, out);
}

// round 11
// speedup vs baseline: 1.0504x; 1.0504x over previous
#include <cuda_runtime.h>

// Problem constants
#define SS        196        // S*S = 14*14
#define DCH       30         // 5*B + C
#define NBATCH    4096
#define NCELLS    (NBATCH * SS)        // 802816
#define IMG       (DCH * SS)           // 5880 floats per image
#define QPB       49                   // s-quads per image (196/4)
#define NQ        (NBATCH * QPB)       // 200704 cls threads
#define BLOCK     128
#define GRID_CLS  (NQ / BLOCK)         // 1568 exactly
#define GRID_BOX  (NCELLS / BLOCK)     // 6272 exactly
#define GRID_ALL  (GRID_CLS + GRID_BOX)
#define LAMBDA_COORD 5.0f
#define LAMBDA_NOOBJ 0.5f

__global__ void zero_kernel(float* __restrict__ out)
{
    out[0] = 0.0f;
}

__global__ void __launch_bounds__(BLOCK, 12) yolo_split_kernel(
    const float* __restrict__ pred,
    const float* __restrict__ tgt,
    float* __restrict__ out)
{
    float loss = 0.0f;

    if (blockIdx.x < GRID_CLS) {
        // ---------------- cls blocks: channels 10..29, pure streaming ----------------
        const int g = blockIdx.x * BLOCK + threadIdx.x;   // < NQ (exact)
        const int n = g / QPB;
        const int q = g - n * QPB;
        const size_t basef = (size_t)n * IMG + q * 4;     // 16B-aligned

        // obj mask from target conf channel (d=4)
        const float4 cf = *(const float4*)(tgt + basef + 4 * SS);

        float4 a = make_float4(0.f, 0.f, 0.f, 0.f);
#pragma unroll
        for (int d = 10; d < DCH; ++d) {
            const float4 p = *(const float4*)(pred + basef + d * SS);
            const float4 t = *(const float4*)(tgt  + basef + d * SS);
            const float dx = p.x - t.x, dy = p.y - t.y;
            const float dz = p.z - t.z, dw = p.w - t.w;
            a.x += dx * dx; a.y += dy * dy;
            a.z += dz * dz; a.w += dw * dw;
        }
        loss = (cf.x > 0.0f ? a.x : 0.0f)
             + (cf.y > 0.0f ? a.y : 0.0f)
             + (cf.z > 0.0f ? a.z : 0.0f)
             + (cf.w > 0.0f ? a.w : 0.0f);
    } else {
        // ---------------- box blocks: channels 0..9, scalar R7 body ----------------
        const int cell = (blockIdx.x - GRID_CLS) * BLOCK + threadIdx.x;  // < NCELLS
        const int n = cell / SS;
        const int s = cell - n * SS;
        const size_t base = (size_t)n * IMG + s;
        const float* __restrict__ pb = pred + base;
        const float* __restrict__ tb = tgt  + base;

        float pp[10], tp[10];
#pragma unroll
        for (int d = 0; d < 10; ++d) {
            pp[d] = pb[d * SS];
            tp[d] = tb[d * SS];
        }

        const float tconf = tp[4];
        const float obj   = (tconf > 0.0f) ? 1.0f : 0.0f;
        const float noobj = (tconf == 0.0f) ? 1.0f : 0.0f;

        // no-object confidence loss (conf channels d=4, d=9)
        const float d0 = pp[4] - tp[4];
        const float d1 = pp[9] - tp[9];
        const float l_noobj = noobj * (d0 * d0 + d1 * d1);

        // IoU of each predicted box vs target box 0
        const float invS = 1.0f / 14.0f;
        const float t_cx = tp[0] * invS, t_cy = tp[1] * invS;
        const float t_ltx = t_cx - 0.5f * tp[2];
        const float t_lty = t_cy - 0.5f * tp[3];
        const float t_rbx = t_cx + 0.5f * tp[2];
        const float t_rby = t_cy + 0.5f * tp[3];
        const float t_area = (t_rbx - t_ltx) * (t_rby - t_lty);

        float iou[2];
#pragma unroll
        for (int b = 0; b < 2; ++b) {
            const float px = pp[5 * b + 0], py = pp[5 * b + 1];
            const float pw = pp[5 * b + 2], ph = pp[5 * b + 3];
            const float p_cx = px * invS, p_cy = py * invS;
            const float p_ltx = p_cx - 0.5f * pw;
            const float p_lty = p_cy - 0.5f * ph;
            const float p_rbx = p_cx + 0.5f * pw;
            const float p_rby = p_cy + 0.5f * ph;
            const float wx = fmaxf(fminf(t_rbx, p_rbx) - fmaxf(t_ltx, p_ltx), 0.0f);
            const float wy = fmaxf(fminf(t_rby, p_rby) - fmaxf(t_lty, p_lty), 0.0f);
            const float inter  = wx * wy;
            const float p_area = (p_rbx - p_ltx) * (p_rby - p_lty);
            float un = t_area + p_area - inter;
            if (un == 0.0f) un = 1.0f;
            iou[b] = inter / un;
        }

        // argmax (strict > so box 0 wins ties)
        const int   r       = (iou[1] > iou[0]) ? 1 : 0;
        const float max_iou = fmaxf(iou[0], iou[1]);

        const float e0 = pp[5 * r + 0] - tp[5 * r + 0];
        const float e1 = pp[5 * r + 1] - tp[5 * r + 1];
        const float e2 = pp[5 * r + 2] - tp[5 * r + 2];
        const float e3 = pp[5 * r + 3] - tp[5 * r + 3];
        const float l_coord = e0 * e0 + e1 * e1 + e2 * e2 + e3 * e3;
        const float ec = pp[5 * r + 4] - max_iou;

        loss = obj * (LAMBDA_COORD * l_coord + ec * ec)
             + LAMBDA_NOOBJ * l_noobj;
    }

    // ---- block reduction, then one fire-and-forget atomicAdd per block ----
    __shared__ float warp_sums[BLOCK / 32];
#pragma unroll
    for (int off = 16; off > 0; off >>= 1)
        loss += __shfl_xor_sync(0xFFFFFFFFu, loss, off);
    const int lane = threadIdx.x & 31;
    const int wid  = threadIdx.x >> 5;
    if (lane == 0) warp_sums[wid] = loss;
    __syncthreads();
    if (wid == 0) {
        float v = (lane < BLOCK / 32) ? warp_sums[lane] : 0.0f;
#pragma unroll
        for (int off = 2; off > 0; off >>= 1)
            v += __shfl_xor_sync(0xFFFFFFFFu, v, off);
        if (lane == 0)
            atomicAdd(out, v * (1.0f / (float)NBATCH));
    }
}

extern "C" void kernel_launch(void* const* d_in, const int* in_sizes, int n_in,
                              void* d_out, int out_size)
{
    const float* pred = (const float*)d_in[0];
    const float* tgt  = (const float*)d_in[1];
    float* out = (float*)d_out;
    zero_kernel<<<1, 1>>>(out);
    yolo_split_kernel<<<GRID_ALL, BLOCK>>>(pred, tgt, out);
}